// round 2
// baseline (speedup 1.0000x reference)
#include <cuda_runtime.h>
#include <math.h>

// ---------------------------------------------------------------------------
// GraphNet: edge MLP (208->128->64) + mean-agg + node MLP (144->128->64)
//           + global MLP (144->128->16)
// fp32 SIMT baseline, fused gather/scatter.
// edge_index is read as int32 (harness narrows int64 -> int32).
// ---------------------------------------------------------------------------

#define FN   64
#define FG   16
#define HD   128
#define K1   208   // FG + 2*FN + FE
#define KN   144   // FG + FN + FEO
#define TILE 64
#define NT   256

#define S_IN1 212  // padded stride for edge input tile (multiple of 4)
#define S_IN2 148  // padded stride for node input tile
#define S_H   132  // padded stride for hidden tile

#define NMAX 100000

__device__ __align__(16) float g_segsum[(size_t)NMAX * 64];
__device__ __align__(16) float g_cnt[NMAX];
__device__ __align__(16) float g_esum[64];
__device__ __align__(16) float g_nsum[64];

// --------------------------------------------------------------------------
__global__ void zero_kernel(int N) {
    size_t i = (size_t)blockIdx.x * blockDim.x + threadIdx.x;
    size_t t4 = (size_t)N * 16;  // N*64 floats as float4
    if (i < t4) ((float4*)g_segsum)[i] = make_float4(0.f, 0.f, 0.f, 0.f);
    if (i < (size_t)N) g_cnt[i] = 0.f;
    if (i < 64) { g_esum[i] = 0.f; g_nsum[i] = 0.f; }
}

// --------------------------------------------------------------------------
// Edge kernel: per 64-edge tile
//   sIn[64][208] = [g | x[row] | x[col] | ea]
//   h = relu(sIn @ W1 + b1)   (64x128)
//   out = h @ W2 + b2         (64x64)
//   scatter: edge_out, atomic seg_sum[row], cnt[row], block-reduced e_sum
// --------------------------------------------------------------------------
extern __shared__ float smem[];

__global__ __launch_bounds__(NT, 2)
void edge_kernel(const float* __restrict__ x, const int* __restrict__ ei,
                 const float* __restrict__ ea, const float* __restrict__ g,
                 const float* __restrict__ W1, const float* __restrict__ b1,
                 const float* __restrict__ W2, const float* __restrict__ b2,
                 float* __restrict__ eout, int E, int N)
{
    float* sH  = smem;                    // 64 * 132
    float* sIn = smem + TILE * S_H;       // 64 * 212
    float* sW1 = sIn + TILE * S_IN1;      // 16 * 128
    float* sW2 = sIn;                     // 128 * 64 (aliased after GEMM1)

    __shared__ int   sRow[TILE];
    __shared__ int   sCol[TILE];
    __shared__ float part[16][64];

    const int tid = threadIdx.x;
    const int e0  = blockIdx.x * TILE;

    if (tid < TILE) {
        int e = e0 + tid;
        int r = 0, c = 0;
        if (e < E) { r = ei[e]; c = ei[E + e]; }
        // defensive clamp: if index dtype assumption is wrong we want a
        // finite rel_err, not an IMA
        r = min(max(r, 0), N - 1);
        c = min(max(c, 0), N - 1);
        sRow[tid] = r;
        sCol[tid] = c;
    }
    __syncthreads();

    // ---- gather: 52 float4 per edge ----
    for (int i = tid; i < TILE * 52; i += NT) {
        int e = i / 52, c = i % 52;
        int ge = e0 + e;
        float4 v = make_float4(0.f, 0.f, 0.f, 0.f);
        if (ge < E) {
            if (c < 4)       v = ((const float4*)g)[c];
            else if (c < 20) v = ((const float4*)(x + (size_t)sRow[e] * FN))[c - 4];
            else if (c < 36) v = ((const float4*)(x + (size_t)sCol[e] * FN))[c - 20];
            else             v = ((const float4*)(ea + (size_t)ge * FN))[c - 36];
        }
        *((float4*)&sIn[e * S_IN1 + c * 4]) = v;
    }
    __syncthreads();

    const int ty = tid >> 4, tx = tid & 15;
    const int er = ty * 4;  // first edge row of this thread

    // ---- GEMM1: h[64][128] = sIn @ W1 ----
    float acc[4][8];
#pragma unroll
    for (int i = 0; i < 4; i++)
#pragma unroll
        for (int j = 0; j < 8; j++) acc[i][j] = 0.f;

    for (int kb = 0; kb < K1; kb += 16) {
#pragma unroll
        for (int l = 0; l < 2; l++) {
            int idx = tid + l * NT;       // 0..511, 32 float4 per row
            int r = idx >> 5, c4 = idx & 31;
            ((float4*)sW1)[idx] = ((const float4*)(W1 + (size_t)(kb + r) * HD))[c4];
        }
        __syncthreads();
#pragma unroll
        for (int k = 0; k < 16; k++) {
            float a0 = sIn[(er + 0) * S_IN1 + kb + k];
            float a1 = sIn[(er + 1) * S_IN1 + kb + k];
            float a2 = sIn[(er + 2) * S_IN1 + kb + k];
            float a3 = sIn[(er + 3) * S_IN1 + kb + k];
            float bv[8];
            *(float4*)&bv[0] = *(const float4*)&sW1[k * HD + tx * 8];
            *(float4*)&bv[4] = *(const float4*)&sW1[k * HD + tx * 8 + 4];
#pragma unroll
            for (int j = 0; j < 8; j++) {
                acc[0][j] += a0 * bv[j];
                acc[1][j] += a1 * bv[j];
                acc[2][j] += a2 * bv[j];
                acc[3][j] += a3 * bv[j];
            }
        }
        __syncthreads();
    }

    // bias + relu -> sH
    {
        const int j0 = tx * 8;
        float bb[8];
        *(float4*)&bb[0] = *(const float4*)&b1[j0];
        *(float4*)&bb[4] = *(const float4*)&b1[j0 + 4];
#pragma unroll
        for (int i = 0; i < 4; i++) {
#pragma unroll
            for (int j = 0; j < 8; j++) {
                float v = acc[i][j] + bb[j];
                acc[i][j] = v > 0.f ? v : 0.f;
            }
            *(float4*)&sH[(er + i) * S_H + j0]     =
                make_float4(acc[i][0], acc[i][1], acc[i][2], acc[i][3]);
            *(float4*)&sH[(er + i) * S_H + j0 + 4] =
                make_float4(acc[i][4], acc[i][5], acc[i][6], acc[i][7]);
        }
    }

    // load W2 (aliases sIn region; all sIn reads are behind the last sync)
    for (int i = tid; i < HD * 64 / 4; i += NT)
        ((float4*)sW2)[i] = ((const float4*)W2)[i];
    __syncthreads();

    // ---- GEMM2: out[64][64] = sH @ W2 ----
    float acc2[4][4];
#pragma unroll
    for (int i = 0; i < 4; i++)
#pragma unroll
        for (int j = 0; j < 4; j++) acc2[i][j] = 0.f;

#pragma unroll 4
    for (int k = 0; k < HD; k++) {
        float a0 = sH[(er + 0) * S_H + k];
        float a1 = sH[(er + 1) * S_H + k];
        float a2 = sH[(er + 2) * S_H + k];
        float a3 = sH[(er + 3) * S_H + k];
        float4 b = *(const float4*)&sW2[k * 64 + tx * 4];
        acc2[0][0] += a0 * b.x; acc2[0][1] += a0 * b.y; acc2[0][2] += a0 * b.z; acc2[0][3] += a0 * b.w;
        acc2[1][0] += a1 * b.x; acc2[1][1] += a1 * b.y; acc2[1][2] += a1 * b.z; acc2[1][3] += a1 * b.w;
        acc2[2][0] += a2 * b.x; acc2[2][1] += a2 * b.y; acc2[2][2] += a2 * b.z; acc2[2][3] += a2 * b.w;
        acc2[3][0] += a3 * b.x; acc2[3][1] += a3 * b.y; acc2[3][2] += a3 * b.z; acc2[3][3] += a3 * b.w;
    }

    // ---- epilogue: write, scatter, reduce ----
    float4 b2v = *(const float4*)&b2[tx * 4];
    float es0 = 0.f, es1 = 0.f, es2 = 0.f, es3 = 0.f;
#pragma unroll
    for (int i = 0; i < 4; i++) {
        int e = er + i, ge = e0 + e;
        if (ge < E) {
            float v0 = acc2[i][0] + b2v.x;
            float v1 = acc2[i][1] + b2v.y;
            float v2 = acc2[i][2] + b2v.z;
            float v3 = acc2[i][3] + b2v.w;
            *(float4*)&eout[(size_t)ge * 64 + tx * 4] = make_float4(v0, v1, v2, v3);
            int r = sRow[e];
            float* sp = &g_segsum[(size_t)r * 64 + tx * 4];
            atomicAdd(sp + 0, v0);
            atomicAdd(sp + 1, v1);
            atomicAdd(sp + 2, v2);
            atomicAdd(sp + 3, v3);
            if (tx == 0) atomicAdd(&g_cnt[r], 1.0f);
            es0 += v0; es1 += v1; es2 += v2; es3 += v3;
        }
    }
    part[ty][tx * 4 + 0] = es0;
    part[ty][tx * 4 + 1] = es1;
    part[ty][tx * 4 + 2] = es2;
    part[ty][tx * 4 + 3] = es3;
    __syncthreads();
    if (tid < 64) {
        float s = 0.f;
#pragma unroll
        for (int t = 0; t < 16; t++) s += part[t][tid];
        atomicAdd(&g_esum[tid], s);
    }
}

// --------------------------------------------------------------------------
// Node kernel: per 64-node tile
//   sIn[64][144] = [g | x[n] | seg_sum[n]/max(cnt,1)]
// --------------------------------------------------------------------------
__global__ __launch_bounds__(NT, 2)
void node_kernel(const float* __restrict__ x, const float* __restrict__ g,
                 const float* __restrict__ W1, const float* __restrict__ b1,
                 const float* __restrict__ W2, const float* __restrict__ b2,
                 float* __restrict__ nout, int N)
{
    float* sH  = smem;                    // 64 * 132
    float* sIn = smem + TILE * S_H;       // 64 * 148
    float* sW1 = sIn + TILE * S_IN2;      // 16 * 128
    float* sW2 = sIn;                     // 128 * 64 aliased

    __shared__ float part[16][64];

    const int tid = threadIdx.x;
    const int n0  = blockIdx.x * TILE;

    // ---- gather: 36 float4 per node ----
    for (int i = tid; i < TILE * 36; i += NT) {
        int e = i / 36, c = i % 36;
        int n = n0 + e;
        float4 v = make_float4(0.f, 0.f, 0.f, 0.f);
        if (n < N) {
            if (c < 4)       v = ((const float4*)g)[c];
            else if (c < 20) v = ((const float4*)(x + (size_t)n * FN))[c - 4];
            else {
                float4 s = ((const float4*)(g_segsum + (size_t)n * 64))[c - 20];
                float inv = 1.0f / fmaxf(g_cnt[n], 1.0f);
                v = make_float4(s.x * inv, s.y * inv, s.z * inv, s.w * inv);
            }
        }
        *((float4*)&sIn[e * S_IN2 + c * 4]) = v;
    }
    __syncthreads();

    const int ty = tid >> 4, tx = tid & 15;
    const int er = ty * 4;

    float acc[4][8];
#pragma unroll
    for (int i = 0; i < 4; i++)
#pragma unroll
        for (int j = 0; j < 8; j++) acc[i][j] = 0.f;

    for (int kb = 0; kb < KN; kb += 16) {
#pragma unroll
        for (int l = 0; l < 2; l++) {
            int idx = tid + l * NT;
            int r = idx >> 5, c4 = idx & 31;
            ((float4*)sW1)[idx] = ((const float4*)(W1 + (size_t)(kb + r) * HD))[c4];
        }
        __syncthreads();
#pragma unroll
        for (int k = 0; k < 16; k++) {
            float a0 = sIn[(er + 0) * S_IN2 + kb + k];
            float a1 = sIn[(er + 1) * S_IN2 + kb + k];
            float a2 = sIn[(er + 2) * S_IN2 + kb + k];
            float a3 = sIn[(er + 3) * S_IN2 + kb + k];
            float bv[8];
            *(float4*)&bv[0] = *(const float4*)&sW1[k * HD + tx * 8];
            *(float4*)&bv[4] = *(const float4*)&sW1[k * HD + tx * 8 + 4];
#pragma unroll
            for (int j = 0; j < 8; j++) {
                acc[0][j] += a0 * bv[j];
                acc[1][j] += a1 * bv[j];
                acc[2][j] += a2 * bv[j];
                acc[3][j] += a3 * bv[j];
            }
        }
        __syncthreads();
    }

    {
        const int j0 = tx * 8;
        float bb[8];
        *(float4*)&bb[0] = *(const float4*)&b1[j0];
        *(float4*)&bb[4] = *(const float4*)&b1[j0 + 4];
#pragma unroll
        for (int i = 0; i < 4; i++) {
#pragma unroll
            for (int j = 0; j < 8; j++) {
                float v = acc[i][j] + bb[j];
                acc[i][j] = v > 0.f ? v : 0.f;
            }
            *(float4*)&sH[(er + i) * S_H + j0]     =
                make_float4(acc[i][0], acc[i][1], acc[i][2], acc[i][3]);
            *(float4*)&sH[(er + i) * S_H + j0 + 4] =
                make_float4(acc[i][4], acc[i][5], acc[i][6], acc[i][7]);
        }
    }

    for (int i = tid; i < HD * 64 / 4; i += NT)
        ((float4*)sW2)[i] = ((const float4*)W2)[i];
    __syncthreads();

    float acc2[4][4];
#pragma unroll
    for (int i = 0; i < 4; i++)
#pragma unroll
        for (int j = 0; j < 4; j++) acc2[i][j] = 0.f;

#pragma unroll 4
    for (int k = 0; k < HD; k++) {
        float a0 = sH[(er + 0) * S_H + k];
        float a1 = sH[(er + 1) * S_H + k];
        float a2 = sH[(er + 2) * S_H + k];
        float a3 = sH[(er + 3) * S_H + k];
        float4 b = *(const float4*)&sW2[k * 64 + tx * 4];
        acc2[0][0] += a0 * b.x; acc2[0][1] += a0 * b.y; acc2[0][2] += a0 * b.z; acc2[0][3] += a0 * b.w;
        acc2[1][0] += a1 * b.x; acc2[1][1] += a1 * b.y; acc2[1][2] += a1 * b.z; acc2[1][3] += a1 * b.w;
        acc2[2][0] += a2 * b.x; acc2[2][1] += a2 * b.y; acc2[2][2] += a2 * b.z; acc2[2][3] += a2 * b.w;
        acc2[3][0] += a3 * b.x; acc2[3][1] += a3 * b.y; acc2[3][2] += a3 * b.z; acc2[3][3] += a3 * b.w;
    }

    float4 b2v = *(const float4*)&b2[tx * 4];
    float es0 = 0.f, es1 = 0.f, es2 = 0.f, es3 = 0.f;
#pragma unroll
    for (int i = 0; i < 4; i++) {
        int e = er + i, n = n0 + e;
        if (n < N) {
            float v0 = acc2[i][0] + b2v.x;
            float v1 = acc2[i][1] + b2v.y;
            float v2 = acc2[i][2] + b2v.z;
            float v3 = acc2[i][3] + b2v.w;
            *(float4*)&nout[(size_t)n * 64 + tx * 4] = make_float4(v0, v1, v2, v3);
            es0 += v0; es1 += v1; es2 += v2; es3 += v3;
        }
    }
    part[ty][tx * 4 + 0] = es0;
    part[ty][tx * 4 + 1] = es1;
    part[ty][tx * 4 + 2] = es2;
    part[ty][tx * 4 + 3] = es3;
    __syncthreads();
    if (tid < 64) {
        float s = 0.f;
#pragma unroll
        for (int t = 0; t < 16; t++) s += part[t][tid];
        atomicAdd(&g_nsum[tid], s);
    }
}

// --------------------------------------------------------------------------
__global__ void global_kernel(const float* __restrict__ g,
                              const float* __restrict__ Wg1, const float* __restrict__ bg1,
                              const float* __restrict__ Wg2, const float* __restrict__ bg2,
                              float* __restrict__ out, int N, int E)
{
    __shared__ float in[KN];
    __shared__ float h[HD];
    int t = threadIdx.x;
    if (t < 64)        in[t] = g_nsum[t] / (float)N;
    else if (t < 128)  in[t] = g_esum[t - 64] / (float)E;
    else if (t < 144)  in[t] = g[t - 128];
    __syncthreads();
    if (t < HD) {
        float s = bg1[t];
        for (int k = 0; k < KN; k++) s += in[k] * Wg1[(size_t)k * HD + t];
        h[t] = fmaxf(s, 0.f);
    }
    __syncthreads();
    if (t < FG) {
        float s = bg2[t];
        for (int k = 0; k < HD; k++) s += h[k] * Wg2[(size_t)k * FG + t];
        out[t] = s;
    }
}

// --------------------------------------------------------------------------
extern "C" void kernel_launch(void* const* d_in, const int* in_sizes, int n_in,
                              void* d_out, int out_size)
{
    const float* x   = (const float*)d_in[0];
    const int*   ei  = (const int*)d_in[1];
    const float* ea  = (const float*)d_in[2];
    const float* g   = (const float*)d_in[3];
    const float* We1 = (const float*)d_in[4];
    const float* be1 = (const float*)d_in[5];
    const float* We2 = (const float*)d_in[6];
    const float* be2 = (const float*)d_in[7];
    const float* Wn1 = (const float*)d_in[8];
    const float* bn1 = (const float*)d_in[9];
    const float* Wn2 = (const float*)d_in[10];
    const float* bn2 = (const float*)d_in[11];
    const float* Wg1 = (const float*)d_in[12];
    const float* bg1 = (const float*)d_in[13];
    const float* Wg2 = (const float*)d_in[14];
    const float* bg2 = (const float*)d_in[15];

    int N = in_sizes[0] / FN;
    int E = in_sizes[1] / 2;

    float* eout = (float*)d_out;
    float* nout = eout + (size_t)E * 64;
    float* gout = nout + (size_t)N * 64;

    const int SMEM_EDGE = (TILE * S_H + TILE * S_IN1 + 16 * HD) * (int)sizeof(float);
    const int SMEM_NODE = (TILE * S_H + TILE * S_IN2 + 16 * HD) * (int)sizeof(float);

    cudaFuncSetAttribute(edge_kernel, cudaFuncAttributeMaxDynamicSharedMemorySize, SMEM_EDGE);
    cudaFuncSetAttribute(node_kernel, cudaFuncAttributeMaxDynamicSharedMemorySize, SMEM_NODE);

    int zthreads = 256;
    int zblocks = (N * 16 + zthreads - 1) / zthreads;
    zero_kernel<<<zblocks, zthreads>>>(N);

    edge_kernel<<<(E + TILE - 1) / TILE, NT, SMEM_EDGE>>>(
        x, ei, ea, g, We1, be1, We2, be2, eout, E, N);

    node_kernel<<<(N + TILE - 1) / TILE, NT, SMEM_NODE>>>(
        x, g, Wn1, bn1, Wn2, bn2, nout, N);

    global_kernel<<<1, 160>>>(g, Wg1, bg1, Wg2, bg2, gout, N, E);
}